// round 1
// baseline (speedup 1.0000x reference)
#include <cuda_runtime.h>
#include <cuda_bf16.h>

// Problem constants
#define TT 4096
#define DD 2048
#define FF 4096
#define EE 8
#define XX 2
#define AA (TT * XX)   // 8192 assignments

// GEMM tiling
#define BM 128
#define BN 64
#define BK 16
#define MAX_TILES (AA / BM + EE)   // 72

// ---------------- scratch (device globals; no allocation) ----------------
__device__ float g_h[(size_t)AA * FF];     // silu(gate)*up, sorted rows [A,F]
__device__ float g_down[(size_t)AA * DD];  // down proj, sorted rows [A,D]
__device__ int g_tile_e[MAX_TILES];
__device__ int g_tile_row0[MAX_TILES];
__device__ int g_tile_cnt[MAX_TILES];
__device__ int g_num_tiles;
__device__ int g_tok[AA];   // sorted position -> source token
__device__ int g_pos[AA];   // assignment -> sorted position

// ---------------- setup: counting sort by expert + tile table ----------------
__global__ void setup_kernel(const int* __restrict__ sel) {
    __shared__ int cnt[EE];
    __shared__ int cur[EE];
    const int tid = threadIdx.x;
    if (tid < EE) cnt[tid] = 0;
    __syncthreads();
    for (int a = tid; a < AA; a += blockDim.x) atomicAdd(&cnt[sel[a]], 1);
    __syncthreads();
    if (tid == 0) {
        int o = 0, nt = 0;
        for (int e = 0; e < EE; e++) {
            cur[e] = o;
            const int c = cnt[e];
            for (int m = 0; m < c; m += BM) {
                g_tile_e[nt]    = e;
                g_tile_row0[nt] = o + m;
                g_tile_cnt[nt]  = (c - m < BM) ? (c - m) : BM;
                nt++;
            }
            o += c;
        }
        g_num_tiles = nt;
    }
    __syncthreads();
    for (int a = tid; a < AA; a += blockDim.x) {
        const int e = sel[a];
        const int p = atomicAdd(&cur[e], 1);
        g_pos[a] = p;
        g_tok[p] = a >> 1;   // XX == 2
    }
}

__device__ __forceinline__ float silu_f(float g) {
    return g / (1.0f + __expf(-g));
}

// ---------------- fused gate+up GEMM: h = silu(X@Wg) * (X@Wu) ----------------
__global__ __launch_bounds__(256, 2)
void gemm_gateup(const float* __restrict__ x,
                 const float* __restrict__ Wg_all,
                 const float* __restrict__ Wu_all) {
    const int mt = blockIdx.x;
    if (mt >= g_num_tiles) return;
    const int e    = g_tile_e[mt];
    const int row0 = g_tile_row0[mt];
    const int cnt  = g_tile_cnt[mt];
    const int n0   = blockIdx.y * BN;

    __shared__ float Xs[BK][BM];
    __shared__ float Bg[BK][BN];
    __shared__ float Bu[BK][BN];

    const float* __restrict__ wg = Wg_all + (size_t)e * DD * FF + n0;
    const float* __restrict__ wu = Wu_all + (size_t)e * DD * FF + n0;

    const int tid = threadIdx.x;
    // X loaders: 64 rows/pass x float4, 2 passes
    const int xr = tid >> 2;
    const int xc = (tid & 3) << 2;
    const int rr0 = (xr < cnt) ? xr : 0;
    const int rr1 = (xr + 64 < cnt) ? (xr + 64) : 0;
    const float* __restrict__ xp0 = x + (size_t)g_tok[row0 + rr0] * DD + xc;
    const float* __restrict__ xp1 = x + (size_t)g_tok[row0 + rr1] * DD + xc;
    // W loaders: 16 rows x 16 float4
    const int wr = tid >> 4;
    const int wc = (tid & 15) << 2;
    // compute mapping: 16x16 threads, each 8 rows x 4 cols
    const int tx = tid & 15;
    const int ty = tid >> 4;

    float accg[8][4], accu[8][4];
#pragma unroll
    for (int i = 0; i < 8; i++)
#pragma unroll
        for (int j = 0; j < 4; j++) { accg[i][j] = 0.f; accu[i][j] = 0.f; }

    for (int k0 = 0; k0 < DD; k0 += BK) {
        const float4 a0 = *(const float4*)(xp0 + k0);
        const float4 a1 = *(const float4*)(xp1 + k0);
        const float4 bg = *(const float4*)(wg + (size_t)(k0 + wr) * FF + wc);
        const float4 bu = *(const float4*)(wu + (size_t)(k0 + wr) * FF + wc);
        __syncthreads();
        Xs[xc + 0][xr] = a0.x; Xs[xc + 1][xr] = a0.y;
        Xs[xc + 2][xr] = a0.z; Xs[xc + 3][xr] = a0.w;
        Xs[xc + 0][xr + 64] = a1.x; Xs[xc + 1][xr + 64] = a1.y;
        Xs[xc + 2][xr + 64] = a1.z; Xs[xc + 3][xr + 64] = a1.w;
        *(float4*)&Bg[wr][wc] = bg;
        *(float4*)&Bu[wr][wc] = bu;
        __syncthreads();
#pragma unroll
        for (int kk = 0; kk < BK; kk++) {
            const float4 a4 = *(const float4*)&Xs[kk][ty * 8];
            const float4 a5 = *(const float4*)&Xs[kk][ty * 8 + 4];
            const float4 g4 = *(const float4*)&Bg[kk][tx * 4];
            const float4 u4 = *(const float4*)&Bu[kk][tx * 4];
            const float am[8] = {a4.x, a4.y, a4.z, a4.w, a5.x, a5.y, a5.z, a5.w};
            const float gm[4] = {g4.x, g4.y, g4.z, g4.w};
            const float um[4] = {u4.x, u4.y, u4.z, u4.w};
#pragma unroll
            for (int i = 0; i < 8; i++)
#pragma unroll
                for (int j = 0; j < 4; j++) {
                    accg[i][j] = fmaf(am[i], gm[j], accg[i][j]);
                    accu[i][j] = fmaf(am[i], um[j], accu[i][j]);
                }
        }
    }

#pragma unroll
    for (int i = 0; i < 8; i++) {
        const int r = ty * 8 + i;
        if (r < cnt) {
            float4 o;
            o.x = silu_f(accg[i][0]) * accu[i][0];
            o.y = silu_f(accg[i][1]) * accu[i][1];
            o.z = silu_f(accg[i][2]) * accu[i][2];
            o.w = silu_f(accg[i][3]) * accu[i][3];
            *(float4*)&g_h[(size_t)(row0 + r) * FF + n0 + tx * 4] = o;
        }
    }
}

// ---------------- down GEMM: down = h @ Wd[e] ----------------
__global__ __launch_bounds__(256, 2)
void gemm_down(const float* __restrict__ Wd_all) {
    const int mt = blockIdx.x;
    if (mt >= g_num_tiles) return;
    const int e    = g_tile_e[mt];
    const int row0 = g_tile_row0[mt];
    const int cnt  = g_tile_cnt[mt];
    const int n0   = blockIdx.y * BN;

    __shared__ float Xs[BK][BM];
    __shared__ float Bs[BK][BN];

    const float* __restrict__ wd = Wd_all + (size_t)e * FF * DD + n0;

    const int tid = threadIdx.x;
    const int xr = tid >> 2;
    const int xc = (tid & 3) << 2;
    const int rr0 = row0 + ((xr < cnt) ? xr : 0);
    const int rr1 = row0 + ((xr + 64 < cnt) ? (xr + 64) : 0);
    const float* __restrict__ xp0 = g_h + (size_t)rr0 * FF + xc;
    const float* __restrict__ xp1 = g_h + (size_t)rr1 * FF + xc;

    const int wr = tid >> 4;
    const int wc = (tid & 15) << 2;
    const int tx = tid & 15;
    const int ty = tid >> 4;

    float acc[8][4];
#pragma unroll
    for (int i = 0; i < 8; i++)
#pragma unroll
        for (int j = 0; j < 4; j++) acc[i][j] = 0.f;

    for (int k0 = 0; k0 < FF; k0 += BK) {
        const float4 a0 = *(const float4*)(xp0 + k0);
        const float4 a1 = *(const float4*)(xp1 + k0);
        const float4 b  = *(const float4*)(wd + (size_t)(k0 + wr) * DD + wc);
        __syncthreads();
        Xs[xc + 0][xr] = a0.x; Xs[xc + 1][xr] = a0.y;
        Xs[xc + 2][xr] = a0.z; Xs[xc + 3][xr] = a0.w;
        Xs[xc + 0][xr + 64] = a1.x; Xs[xc + 1][xr + 64] = a1.y;
        Xs[xc + 2][xr + 64] = a1.z; Xs[xc + 3][xr + 64] = a1.w;
        *(float4*)&Bs[wr][wc] = b;
        __syncthreads();
#pragma unroll
        for (int kk = 0; kk < BK; kk++) {
            const float4 a4 = *(const float4*)&Xs[kk][ty * 8];
            const float4 a5 = *(const float4*)&Xs[kk][ty * 8 + 4];
            const float4 b4 = *(const float4*)&Bs[kk][tx * 4];
            const float am[8] = {a4.x, a4.y, a4.z, a4.w, a5.x, a5.y, a5.z, a5.w};
            const float bm[4] = {b4.x, b4.y, b4.z, b4.w};
#pragma unroll
            for (int i = 0; i < 8; i++)
#pragma unroll
                for (int j = 0; j < 4; j++)
                    acc[i][j] = fmaf(am[i], bm[j], acc[i][j]);
        }
    }

#pragma unroll
    for (int i = 0; i < 8; i++) {
        const int r = ty * 8 + i;
        if (r < cnt) {
            float4 o;
            o.x = acc[i][0]; o.y = acc[i][1]; o.z = acc[i][2]; o.w = acc[i][3];
            *(float4*)&g_down[(size_t)(row0 + r) * DD + n0 + tx * 4] = o;
        }
    }
}

// ---------------- combine: out[t] = w0*down[pos(t,0)] + w1*down[pos(t,1)] ----------------
__global__ void combine_kernel(const float* __restrict__ rw, float* __restrict__ out) {
    const int i = blockIdx.x * blockDim.x + threadIdx.x;   // over TT*DD/4
    if (i >= TT * (DD / 4)) return;
    const int t = i / (DD / 4);
    const int c = (i % (DD / 4)) * 4;
    const int p0 = g_pos[t * 2 + 0];
    const int p1 = g_pos[t * 2 + 1];
    const float w0 = rw[t * 2 + 0];
    const float w1 = rw[t * 2 + 1];
    const float4 a = *(const float4*)&g_down[(size_t)p0 * DD + c];
    const float4 b = *(const float4*)&g_down[(size_t)p1 * DD + c];
    float4 o;
    o.x = w0 * a.x + w1 * b.x;
    o.y = w0 * a.y + w1 * b.y;
    o.z = w0 * a.z + w1 * b.z;
    o.w = w0 * a.w + w1 * b.w;
    *(float4*)&out[(size_t)t * DD + c] = o;
}

extern "C" void kernel_launch(void* const* d_in, const int* in_sizes, int n_in,
                              void* d_out, int out_size) {
    const float* x   = (const float*)d_in[0];  // [T,D]
    const float* rw  = (const float*)d_in[1];  // [T,X]
    const int*   sel = (const int*)d_in[2];    // [T,X]
    const float* Wg  = (const float*)d_in[3];  // [E,D,F]
    const float* Wu  = (const float*)d_in[4];  // [E,D,F]
    const float* Wd  = (const float*)d_in[5];  // [E,F,D]
    float* out = (float*)d_out;

    setup_kernel<<<1, 256>>>(sel);
    gemm_gateup<<<dim3(MAX_TILES, FF / BN), 256>>>(x, Wg, Wu);
    gemm_down<<<dim3(MAX_TILES, DD / BN), 256>>>(Wd);
    combine_kernel<<<(TT * (DD / 4) + 255) / 256, 256>>>(rw, out);
}

// round 6
// speedup vs baseline: 2.8855x; 2.8855x over previous
#include <cuda_runtime.h>
#include <cuda_fp16.h>
#include <mma.h>

using namespace nvcuda;

#define TT 4096
#define DD 2048
#define FF 4096
#define EE 8
#define XX 2
#define AA (TT * XX)

#define BM 128
#define BN 64
#define BK 16
#define ALD 24                        // A smem ldm (halves), 48B rows
#define BLD 72                        // B smem ldm (halves), 144B rows
#define SLD 20                        // scratch ldm (floats)
#define MAX_TILES (AA / BM + EE)      // 72

// ---------------- scratch (device globals; ~192MB, same footprint as passing round 1) ----------------
__device__ __align__(128) float g_h[(size_t)AA * FF];     // silu(gate)*up, sorted rows
__device__ __align__(128) float g_down[(size_t)AA * DD];  // down output, sorted rows
__device__ int g_tile_e[MAX_TILES];
__device__ int g_tile_row0[MAX_TILES];
__device__ int g_tile_cnt[MAX_TILES];
__device__ int g_num_tiles;
__device__ int g_tok[AA];
__device__ int g_pos[AA];

// ---------------- setup: counting sort + tile table (proven in round 1) ----------------
__global__ void setup_kernel(const int* __restrict__ sel) {
    __shared__ int cnt[EE];
    __shared__ int cur[EE];
    const int tid = threadIdx.x;
    if (tid < EE) cnt[tid] = 0;
    __syncthreads();
    for (int a = tid; a < AA; a += blockDim.x) atomicAdd(&cnt[sel[a]], 1);
    __syncthreads();
    if (tid == 0) {
        int o = 0, nt = 0;
        for (int e = 0; e < EE; e++) {
            cur[e] = o;
            const int c = cnt[e];
            for (int m = 0; m < c; m += BM) {
                g_tile_e[nt] = e;
                g_tile_row0[nt] = o + m;
                g_tile_cnt[nt] = (c - m < BM) ? (c - m) : BM;
                nt++;
            }
            o += c;
        }
        g_num_tiles = nt;
    }
    __syncthreads();
    for (int a = tid; a < AA; a += blockDim.x) {
        const int e = sel[a];
        const int p = atomicAdd(&cur[e], 1);
        g_pos[a] = p;
        g_tok[p] = a >> 1;
    }
}

__device__ __forceinline__ void split8(const float4 v0, const float4 v1, uint4& hi, uint4& lo) {
    __half h[8], l[8];
    const float f[8] = {v0.x, v0.y, v0.z, v0.w, v1.x, v1.y, v1.z, v1.w};
#pragma unroll
    for (int i = 0; i < 8; i++) {
        h[i] = __float2half_rn(f[i]);
        l[i] = __float2half_rn(f[i] - __half2float(h[i]));
    }
    hi = *(const uint4*)h;
    lo = *(const uint4*)l;
}
__device__ __forceinline__ uint2 pack4(const float4 v) {
    __half h[4] = {__float2half_rn(v.x), __float2half_rn(v.y),
                   __float2half_rn(v.z), __float2half_rn(v.w)};
    return *(const uint2*)h;
}

// ================= fused gate+up GEMM (wmma fp16, A hi/lo split) =================
__global__ __launch_bounds__(256) void gemm_gateup(const float* __restrict__ x,
                                                   const float* __restrict__ Wg,
                                                   const float* __restrict__ Wu) {
    __shared__ __align__(16) __half As[2][2][BM * ALD];   // [buf][hi/lo]
    __shared__ __align__(16) __half Bsm[2][2][BK * BLD];  // [buf][gate/up]
    __shared__ __align__(16) float scr[8][16 * SLD];

    const int mt = blockIdx.x;
    if (mt >= g_num_tiles) return;
    const int e = g_tile_e[mt];
    const int row0 = g_tile_row0[mt];
    const int cnt = g_tile_cnt[mt];
    const int n0 = blockIdx.y * BN;
    const int tid = threadIdx.x;
    const int wid = tid >> 5;
    const int lane = tid & 31;
    const int wm0 = (wid & 3) * 32;
    const int wn0 = (wid >> 2) * 32;

    // A loader: 128 rows x 2 half-rows of 8 floats
    const int lr = tid >> 1, lc = (tid & 1) * 8;
    const int rowc = (lr < cnt) ? lr : 0;
    const float* pa = x + (size_t)g_tok[row0 + rowc] * DD + lc;
    // B loader: 16 k-rows x 16 chunks of 4 floats
    const int bk = tid >> 4, bn = (tid & 15) * 4;
    const float* pg = Wg + ((size_t)e * DD + bk) * FF + n0 + bn;
    const float* pu = Wu + ((size_t)e * DD + bk) * FF + n0 + bn;
    const int aoff = lr * ALD + lc;
    const int boff = bk * BLD + bn;

    wmma::fragment<wmma::accumulator, 16, 16, 16, float> accg[2][2], accu[2][2];
#pragma unroll
    for (int mi = 0; mi < 2; mi++)
#pragma unroll
        for (int nj = 0; nj < 2; nj++) {
            wmma::fill_fragment(accg[mi][nj], 0.0f);
            wmma::fill_fragment(accu[mi][nj], 0.0f);
        }

    const int NC = DD / BK;  // 128

    // prime buffer 0
    {
        uint4 hi, lo;
        split8(*(const float4*)pa, *(const float4*)(pa + 4), hi, lo);
        *(uint4*)&As[0][0][aoff] = hi;
        *(uint4*)&As[0][1][aoff] = lo;
        *(uint2*)&Bsm[0][0][boff] = pack4(*(const float4*)pg);
        *(uint2*)&Bsm[0][1][boff] = pack4(*(const float4*)pu);
    }
    __syncthreads();

    for (int c = 0; c < NC; c++) {
        const int buf = c & 1;
        float4 va0, va1, vg, vu;
        if (c + 1 < NC) {
            va0 = *(const float4*)(pa + (c + 1) * BK);
            va1 = *(const float4*)(pa + (c + 1) * BK + 4);
            vg  = *(const float4*)(pg + (size_t)(c + 1) * BK * FF);
            vu  = *(const float4*)(pu + (size_t)(c + 1) * BK * FF);
        }

        wmma::fragment<wmma::matrix_a, 16, 16, 16, __half, wmma::row_major> aH[2], aL[2];
        wmma::fragment<wmma::matrix_b, 16, 16, 16, __half, wmma::row_major> bg[2], bu[2];
#pragma unroll
        for (int mi = 0; mi < 2; mi++) {
            wmma::load_matrix_sync(aH[mi], &As[buf][0][(wm0 + mi * 16) * ALD], ALD);
            wmma::load_matrix_sync(aL[mi], &As[buf][1][(wm0 + mi * 16) * ALD], ALD);
        }
#pragma unroll
        for (int nj = 0; nj < 2; nj++) {
            wmma::load_matrix_sync(bg[nj], &Bsm[buf][0][wn0 + nj * 16], BLD);
            wmma::load_matrix_sync(bu[nj], &Bsm[buf][1][wn0 + nj * 16], BLD);
        }
#pragma unroll
        for (int mi = 0; mi < 2; mi++)
#pragma unroll
            for (int nj = 0; nj < 2; nj++) {
                wmma::mma_sync(accg[mi][nj], aH[mi], bg[nj], accg[mi][nj]);
                wmma::mma_sync(accg[mi][nj], aL[mi], bg[nj], accg[mi][nj]);
                wmma::mma_sync(accu[mi][nj], aH[mi], bu[nj], accu[mi][nj]);
                wmma::mma_sync(accu[mi][nj], aL[mi], bu[nj], accu[mi][nj]);
            }

        if (c + 1 < NC) {
            const int nb = (c + 1) & 1;
            uint4 hi, lo;
            split8(va0, va1, hi, lo);
            *(uint4*)&As[nb][0][aoff] = hi;
            *(uint4*)&As[nb][1][aoff] = lo;
            *(uint2*)&Bsm[nb][0][boff] = pack4(vg);
            *(uint2*)&Bsm[nb][1][boff] = pack4(vu);
        }
        __syncthreads();
    }

    // epilogue: h = silu(g) * u -> g_h (fp32), via per-warp scratch
    const int er = lane >> 1, ec = (lane & 1) * 8;
#pragma unroll
    for (int mi = 0; mi < 2; mi++)
#pragma unroll
        for (int nj = 0; nj < 2; nj++) {
            float gv[8], uv[8];
            wmma::store_matrix_sync(&scr[wid][0], accg[mi][nj], SLD, wmma::mem_row_major);
            __syncwarp();
#pragma unroll
            for (int q = 0; q < 8; q++) gv[q] = scr[wid][er * SLD + ec + q];
            __syncwarp();
            wmma::store_matrix_sync(&scr[wid][0], accu[mi][nj], SLD, wmma::mem_row_major);
            __syncwarp();
#pragma unroll
            for (int q = 0; q < 8; q++) uv[q] = scr[wid][er * SLD + ec + q];
            __syncwarp();
            const int rin = wm0 + mi * 16 + er;
            if (rin < cnt) {
                float* dst = g_h + (size_t)(row0 + rin) * FF + n0 + wn0 + nj * 16 + ec;
                float o[8];
#pragma unroll
                for (int q = 0; q < 8; q++)
                    o[q] = (gv[q] / (1.0f + __expf(-gv[q]))) * uv[q];
                *(float4*)dst = make_float4(o[0], o[1], o[2], o[3]);
                *(float4*)(dst + 4) = make_float4(o[4], o[5], o[6], o[7]);
            }
        }
}

// ================= down GEMM (wmma fp16, A hi/lo split) =================
__global__ __launch_bounds__(256) void gemm_down(const float* __restrict__ Wd) {
    __shared__ __align__(16) __half As[2][2][BM * ALD];
    __shared__ __align__(16) __half Bsm[2][BK * BLD];
    __shared__ __align__(16) float scr[8][16 * SLD];

    const int mt = blockIdx.x;
    if (mt >= g_num_tiles) return;
    const int e = g_tile_e[mt];
    const int row0 = g_tile_row0[mt];
    const int cnt = g_tile_cnt[mt];
    const int n0 = blockIdx.y * BN;
    const int tid = threadIdx.x;
    const int wid = tid >> 5;
    const int lane = tid & 31;
    const int wm0 = (wid & 3) * 32;
    const int wn0 = (wid >> 2) * 32;

    const int lr = tid >> 1, lc = (tid & 1) * 8;
    const int rowc = (lr < cnt) ? lr : 0;
    const float* pa = g_h + (size_t)(row0 + rowc) * FF + lc;
    const int bk = tid >> 4, bn = (tid & 15) * 4;
    const float* pb = Wd + ((size_t)e * FF + bk) * DD + n0 + bn;
    const int aoff = lr * ALD + lc;
    const int boff = bk * BLD + bn;

    wmma::fragment<wmma::accumulator, 16, 16, 16, float> acc[2][2];
#pragma unroll
    for (int mi = 0; mi < 2; mi++)
#pragma unroll
        for (int nj = 0; nj < 2; nj++) wmma::fill_fragment(acc[mi][nj], 0.0f);

    const int NC = FF / BK;  // 256

    {
        uint4 hi, lo;
        split8(*(const float4*)pa, *(const float4*)(pa + 4), hi, lo);
        *(uint4*)&As[0][0][aoff] = hi;
        *(uint4*)&As[0][1][aoff] = lo;
        *(uint2*)&Bsm[0][boff] = pack4(*(const float4*)pb);
    }
    __syncthreads();

    for (int c = 0; c < NC; c++) {
        const int buf = c & 1;
        float4 va0, va1, vb;
        if (c + 1 < NC) {
            va0 = *(const float4*)(pa + (c + 1) * BK);
            va1 = *(const float4*)(pa + (c + 1) * BK + 4);
            vb  = *(const float4*)(pb + (size_t)(c + 1) * BK * DD);
        }

        wmma::fragment<wmma::matrix_a, 16, 16, 16, __half, wmma::row_major> aH[2], aL[2];
        wmma::fragment<wmma::matrix_b, 16, 16, 16, __half, wmma::row_major> bd[2];
#pragma unroll
        for (int mi = 0; mi < 2; mi++) {
            wmma::load_matrix_sync(aH[mi], &As[buf][0][(wm0 + mi * 16) * ALD], ALD);
            wmma::load_matrix_sync(aL[mi], &As[buf][1][(wm0 + mi * 16) * ALD], ALD);
        }
#pragma unroll
        for (int nj = 0; nj < 2; nj++)
            wmma::load_matrix_sync(bd[nj], &Bsm[buf][wn0 + nj * 16], BLD);
#pragma unroll
        for (int mi = 0; mi < 2; mi++)
#pragma unroll
            for (int nj = 0; nj < 2; nj++) {
                wmma::mma_sync(acc[mi][nj], aH[mi], bd[nj], acc[mi][nj]);
                wmma::mma_sync(acc[mi][nj], aL[mi], bd[nj], acc[mi][nj]);
            }

        if (c + 1 < NC) {
            const int nb = (c + 1) & 1;
            uint4 hi, lo;
            split8(va0, va1, hi, lo);
            *(uint4*)&As[nb][0][aoff] = hi;
            *(uint4*)&As[nb][1][aoff] = lo;
            *(uint2*)&Bsm[nb][boff] = pack4(vb);
        }
        __syncthreads();
    }

    const int er = lane >> 1, ec = (lane & 1) * 8;
#pragma unroll
    for (int mi = 0; mi < 2; mi++)
#pragma unroll
        for (int nj = 0; nj < 2; nj++) {
            wmma::store_matrix_sync(&scr[wid][0], acc[mi][nj], SLD, wmma::mem_row_major);
            __syncwarp();
            float o[8];
#pragma unroll
            for (int q = 0; q < 8; q++) o[q] = scr[wid][er * SLD + ec + q];
            __syncwarp();
            const int rin = wm0 + mi * 16 + er;
            if (rin < cnt) {
                float* dst = g_down + (size_t)(row0 + rin) * DD + n0 + wn0 + nj * 16 + ec;
                *(float4*)dst = make_float4(o[0], o[1], o[2], o[3]);
                *(float4*)(dst + 4) = make_float4(o[4], o[5], o[6], o[7]);
            }
        }
}

// ---------------- combine (proven in round 1) ----------------
__global__ void combine_kernel(const float* __restrict__ rw, float* __restrict__ out) {
    const int i = blockIdx.x * blockDim.x + threadIdx.x;
    if (i >= TT * (DD / 4)) return;
    const int t = i / (DD / 4);
    const int c = (i % (DD / 4)) * 4;
    const int p0 = g_pos[t * 2 + 0];
    const int p1 = g_pos[t * 2 + 1];
    const float w0 = rw[t * 2 + 0];
    const float w1 = rw[t * 2 + 1];
    const float4 a = *(const float4*)&g_down[(size_t)p0 * DD + c];
    const float4 b = *(const float4*)&g_down[(size_t)p1 * DD + c];
    float4 o;
    o.x = w0 * a.x + w1 * b.x;
    o.y = w0 * a.y + w1 * b.y;
    o.z = w0 * a.z + w1 * b.z;
    o.w = w0 * a.w + w1 * b.w;
    *(float4*)&out[(size_t)t * DD + c] = o;
}

extern "C" void kernel_launch(void* const* d_in, const int* in_sizes, int n_in,
                              void* d_out, int out_size) {
    const float* x   = (const float*)d_in[0];
    const float* rw  = (const float*)d_in[1];
    const int*   sel = (const int*)d_in[2];
    const float* Wg  = (const float*)d_in[3];
    const float* Wu  = (const float*)d_in[4];
    const float* Wd  = (const float*)d_in[5];
    float* out = (float*)d_out;

    setup_kernel<<<1, 256>>>(sel);
    gemm_gateup<<<dim3(MAX_TILES, FF / BN), 256>>>(x, Wg, Wu);
    gemm_down<<<dim3(MAX_TILES, DD / BN), 256>>>(Wd);
    combine_kernel<<<(TT * (DD / 4) + 255) / 256, 256>>>(rw, out);
}

// round 7
// speedup vs baseline: 3.7801x; 1.3101x over previous
#include <cuda_runtime.h>
#include <cuda_fp16.h>
#include <mma.h>

using namespace nvcuda;

#define TT 4096
#define DD 2048
#define FF 4096
#define EE 8
#define XX 2
#define AA (TT * XX)

#define BM 128
#define BN 64
#define BK 16
#define ALD 24                        // A smem ldm (halves), 48B rows
#define BLD 72                        // B smem ldm (halves), 144B rows
#define SLD 20                        // scratch ldm (floats)
#define MAX_TILES (AA / BM + EE)      // 72

// ---------------- scratch (device globals; ~192MB proven footprint) ----------------
__device__ __align__(128) float g_h[(size_t)AA * FF];     // silu(gate)*up, sorted rows
__device__ __align__(128) float g_down[(size_t)AA * DD];  // down output, sorted rows
__device__ int g_tile_e[MAX_TILES];
__device__ int g_tile_row0[MAX_TILES];
__device__ int g_tile_cnt[MAX_TILES];
__device__ int g_num_tiles;
__device__ int g_tok[AA];
__device__ int g_pos[AA];

// ---------------- setup: counting sort + tile table (proven) ----------------
__global__ void setup_kernel(const int* __restrict__ sel) {
    __shared__ int cnt[EE];
    __shared__ int cur[EE];
    const int tid = threadIdx.x;
    if (tid < EE) cnt[tid] = 0;
    __syncthreads();
    for (int a = tid; a < AA; a += blockDim.x) atomicAdd(&cnt[sel[a]], 1);
    __syncthreads();
    if (tid == 0) {
        int o = 0, nt = 0;
        for (int e = 0; e < EE; e++) {
            cur[e] = o;
            const int c = cnt[e];
            for (int m = 0; m < c; m += BM) {
                g_tile_e[nt] = e;
                g_tile_row0[nt] = o + m;
                g_tile_cnt[nt] = (c - m < BM) ? (c - m) : BM;
                nt++;
            }
            o += c;
        }
        g_num_tiles = nt;
    }
    __syncthreads();
    for (int a = tid; a < AA; a += blockDim.x) {
        const int e = sel[a];
        const int p = atomicAdd(&cur[e], 1);
        g_pos[a] = p;
        g_tok[p] = a >> 1;
    }
}

__device__ __forceinline__ uint4 pack8(const float4 v0, const float4 v1) {
    __half h[8] = {__float2half_rn(v0.x), __float2half_rn(v0.y),
                   __float2half_rn(v0.z), __float2half_rn(v0.w),
                   __float2half_rn(v1.x), __float2half_rn(v1.y),
                   __float2half_rn(v1.z), __float2half_rn(v1.w)};
    return *(const uint4*)h;
}
__device__ __forceinline__ uint2 pack4(const float4 v) {
    __half h[4] = {__float2half_rn(v.x), __float2half_rn(v.y),
                   __float2half_rn(v.z), __float2half_rn(v.w)};
    return *(const uint2*)h;
}

// ================= fused gate+up GEMM (wmma fp16) =================
__global__ __launch_bounds__(256) void gemm_gateup(const float* __restrict__ x,
                                                   const float* __restrict__ Wg,
                                                   const float* __restrict__ Wu) {
    __shared__ __align__(16) __half As[2][BM * ALD];      // [buf]
    __shared__ __align__(16) __half Bsm[2][2][BK * BLD];  // [buf][gate/up]
    __shared__ __align__(16) float scr[8][16 * SLD];

    const int mt = blockIdx.x;
    if (mt >= g_num_tiles) return;
    const int e = g_tile_e[mt];
    const int row0 = g_tile_row0[mt];
    const int cnt = g_tile_cnt[mt];
    const int n0 = blockIdx.y * BN;
    const int tid = threadIdx.x;
    const int wid = tid >> 5;
    const int lane = tid & 31;
    const int wm0 = (wid & 3) * 32;
    const int wn0 = (wid >> 2) * 32;

    // A loader: 128 rows x 2 half-rows of 8 floats
    const int lr = tid >> 1, lc = (tid & 1) * 8;
    const int rowc = (lr < cnt) ? lr : 0;
    const float* pa = x + (size_t)g_tok[row0 + rowc] * DD + lc;
    // B loader: 16 k-rows x 16 chunks of 4 floats
    const int bk = tid >> 4, bn = (tid & 15) * 4;
    const float* pg = Wg + ((size_t)e * DD + bk) * FF + n0 + bn;
    const float* pu = Wu + ((size_t)e * DD + bk) * FF + n0 + bn;
    const int aoff = lr * ALD + lc;
    const int boff = bk * BLD + bn;

    wmma::fragment<wmma::accumulator, 16, 16, 16, float> accg[2][2], accu[2][2];
#pragma unroll
    for (int mi = 0; mi < 2; mi++)
#pragma unroll
        for (int nj = 0; nj < 2; nj++) {
            wmma::fill_fragment(accg[mi][nj], 0.0f);
            wmma::fill_fragment(accu[mi][nj], 0.0f);
        }

    const int NC = DD / BK;  // 128

    // prime buffer 0
    *(uint4*)&As[0][aoff] = pack8(*(const float4*)pa, *(const float4*)(pa + 4));
    *(uint2*)&Bsm[0][0][boff] = pack4(*(const float4*)pg);
    *(uint2*)&Bsm[0][1][boff] = pack4(*(const float4*)pu);
    __syncthreads();

    for (int c = 0; c < NC; c++) {
        const int buf = c & 1;
        float4 va0, va1, vg, vu;
        if (c + 1 < NC) {
            va0 = *(const float4*)(pa + (c + 1) * BK);
            va1 = *(const float4*)(pa + (c + 1) * BK + 4);
            vg  = *(const float4*)(pg + (size_t)(c + 1) * BK * FF);
            vu  = *(const float4*)(pu + (size_t)(c + 1) * BK * FF);
        }

        wmma::fragment<wmma::matrix_a, 16, 16, 16, __half, wmma::row_major> aF[2];
        wmma::fragment<wmma::matrix_b, 16, 16, 16, __half, wmma::row_major> bg[2], bu[2];
#pragma unroll
        for (int mi = 0; mi < 2; mi++)
            wmma::load_matrix_sync(aF[mi], &As[buf][(wm0 + mi * 16) * ALD], ALD);
#pragma unroll
        for (int nj = 0; nj < 2; nj++) {
            wmma::load_matrix_sync(bg[nj], &Bsm[buf][0][wn0 + nj * 16], BLD);
            wmma::load_matrix_sync(bu[nj], &Bsm[buf][1][wn0 + nj * 16], BLD);
        }
#pragma unroll
        for (int mi = 0; mi < 2; mi++)
#pragma unroll
            for (int nj = 0; nj < 2; nj++) {
                wmma::mma_sync(accg[mi][nj], aF[mi], bg[nj], accg[mi][nj]);
                wmma::mma_sync(accu[mi][nj], aF[mi], bu[nj], accu[mi][nj]);
            }

        if (c + 1 < NC) {
            const int nb = (c + 1) & 1;
            *(uint4*)&As[nb][aoff] = pack8(va0, va1);
            *(uint2*)&Bsm[nb][0][boff] = pack4(vg);
            *(uint2*)&Bsm[nb][1][boff] = pack4(vu);
        }
        __syncthreads();
    }

    // epilogue: h = silu(g) * u -> g_h (fp32), via per-warp scratch
    const int er = lane >> 1, ec = (lane & 1) * 8;
#pragma unroll
    for (int mi = 0; mi < 2; mi++)
#pragma unroll
        for (int nj = 0; nj < 2; nj++) {
            float gv[8], uv[8];
            wmma::store_matrix_sync(&scr[wid][0], accg[mi][nj], SLD, wmma::mem_row_major);
            __syncwarp();
#pragma unroll
            for (int q = 0; q < 8; q++) gv[q] = scr[wid][er * SLD + ec + q];
            __syncwarp();
            wmma::store_matrix_sync(&scr[wid][0], accu[mi][nj], SLD, wmma::mem_row_major);
            __syncwarp();
#pragma unroll
            for (int q = 0; q < 8; q++) uv[q] = scr[wid][er * SLD + ec + q];
            __syncwarp();
            const int rin = wm0 + mi * 16 + er;
            if (rin < cnt) {
                float* dst = g_h + (size_t)(row0 + rin) * FF + n0 + wn0 + nj * 16 + ec;
                float o[8];
#pragma unroll
                for (int q = 0; q < 8; q++)
                    o[q] = (gv[q] / (1.0f + __expf(-gv[q]))) * uv[q];
                *(float4*)dst = make_float4(o[0], o[1], o[2], o[3]);
                *(float4*)(dst + 4) = make_float4(o[4], o[5], o[6], o[7]);
            }
        }
}

// ================= down GEMM (wmma fp16) =================
__global__ __launch_bounds__(256) void gemm_down(const float* __restrict__ Wd) {
    __shared__ __align__(16) __half As[2][BM * ALD];
    __shared__ __align__(16) __half Bsm[2][BK * BLD];
    __shared__ __align__(16) float scr[8][16 * SLD];

    const int mt = blockIdx.x;
    if (mt >= g_num_tiles) return;
    const int e = g_tile_e[mt];
    const int row0 = g_tile_row0[mt];
    const int cnt = g_tile_cnt[mt];
    const int n0 = blockIdx.y * BN;
    const int tid = threadIdx.x;
    const int wid = tid >> 5;
    const int lane = tid & 31;
    const int wm0 = (wid & 3) * 32;
    const int wn0 = (wid >> 2) * 32;

    const int lr = tid >> 1, lc = (tid & 1) * 8;
    const int rowc = (lr < cnt) ? lr : 0;
    const float* pa = g_h + (size_t)(row0 + rowc) * FF + lc;
    const int bk = tid >> 4, bn = (tid & 15) * 4;
    const float* pb = Wd + ((size_t)e * FF + bk) * DD + n0 + bn;
    const int aoff = lr * ALD + lc;
    const int boff = bk * BLD + bn;

    wmma::fragment<wmma::accumulator, 16, 16, 16, float> acc[2][2];
#pragma unroll
    for (int mi = 0; mi < 2; mi++)
#pragma unroll
        for (int nj = 0; nj < 2; nj++) wmma::fill_fragment(acc[mi][nj], 0.0f);

    const int NC = FF / BK;  // 256

    *(uint4*)&As[0][aoff] = pack8(*(const float4*)pa, *(const float4*)(pa + 4));
    *(uint2*)&Bsm[0][boff] = pack4(*(const float4*)pb);
    __syncthreads();

    for (int c = 0; c < NC; c++) {
        const int buf = c & 1;
        float4 va0, va1, vb;
        if (c + 1 < NC) {
            va0 = *(const float4*)(pa + (c + 1) * BK);
            va1 = *(const float4*)(pa + (c + 1) * BK + 4);
            vb  = *(const float4*)(pb + (size_t)(c + 1) * BK * DD);
        }

        wmma::fragment<wmma::matrix_a, 16, 16, 16, __half, wmma::row_major> aF[2];
        wmma::fragment<wmma::matrix_b, 16, 16, 16, __half, wmma::row_major> bd[2];
#pragma unroll
        for (int mi = 0; mi < 2; mi++)
            wmma::load_matrix_sync(aF[mi], &As[buf][(wm0 + mi * 16) * ALD], ALD);
#pragma unroll
        for (int nj = 0; nj < 2; nj++)
            wmma::load_matrix_sync(bd[nj], &Bsm[buf][wn0 + nj * 16], BLD);
#pragma unroll
        for (int mi = 0; mi < 2; mi++)
#pragma unroll
            for (int nj = 0; nj < 2; nj++)
                wmma::mma_sync(acc[mi][nj], aF[mi], bd[nj], acc[mi][nj]);

        if (c + 1 < NC) {
            const int nb = (c + 1) & 1;
            *(uint4*)&As[nb][aoff] = pack8(va0, va1);
            *(uint2*)&Bsm[nb][boff] = pack4(vb);
        }
        __syncthreads();
    }

    const int er = lane >> 1, ec = (lane & 1) * 8;
#pragma unroll
    for (int mi = 0; mi < 2; mi++)
#pragma unroll
        for (int nj = 0; nj < 2; nj++) {
            wmma::store_matrix_sync(&scr[wid][0], acc[mi][nj], SLD, wmma::mem_row_major);
            __syncwarp();
            float o[8];
#pragma unroll
            for (int q = 0; q < 8; q++) o[q] = scr[wid][er * SLD + ec + q];
            __syncwarp();
            const int rin = wm0 + mi * 16 + er;
            if (rin < cnt) {
                float* dst = g_down + (size_t)(row0 + rin) * DD + n0 + wn0 + nj * 16 + ec;
                *(float4*)dst = make_float4(o[0], o[1], o[2], o[3]);
                *(float4*)(dst + 4) = make_float4(o[4], o[5], o[6], o[7]);
            }
        }
}

// ---------------- combine (proven) ----------------
__global__ void combine_kernel(const float* __restrict__ rw, float* __restrict__ out) {
    const int i = blockIdx.x * blockDim.x + threadIdx.x;
    if (i >= TT * (DD / 4)) return;
    const int t = i / (DD / 4);
    const int c = (i % (DD / 4)) * 4;
    const int p0 = g_pos[t * 2 + 0];
    const int p1 = g_pos[t * 2 + 1];
    const float w0 = rw[t * 2 + 0];
    const float w1 = rw[t * 2 + 1];
    const float4 a = *(const float4*)&g_down[(size_t)p0 * DD + c];
    const float4 b = *(const float4*)&g_down[(size_t)p1 * DD + c];
    float4 o;
    o.x = w0 * a.x + w1 * b.x;
    o.y = w0 * a.y + w1 * b.y;
    o.z = w0 * a.z + w1 * b.z;
    o.w = w0 * a.w + w1 * b.w;
    *(float4*)&out[(size_t)t * DD + c] = o;
}

extern "C" void kernel_launch(void* const* d_in, const int* in_sizes, int n_in,
                              void* d_out, int out_size) {
    const float* x   = (const float*)d_in[0];
    const float* rw  = (const float*)d_in[1];
    const int*   sel = (const int*)d_in[2];
    const float* Wg  = (const float*)d_in[3];
    const float* Wu  = (const float*)d_in[4];
    const float* Wd  = (const float*)d_in[5];
    float* out = (float*)d_out;

    setup_kernel<<<1, 256>>>(sel);
    gemm_gateup<<<dim3(MAX_TILES, FF / BN), 256>>>(x, Wg, Wu);
    gemm_down<<<dim3(MAX_TILES, DD / BN), 256>>>(Wd);
    combine_kernel<<<(TT * (DD / 4) + 255) / 256, 256>>>(rw, out);
}